// round 9
// baseline (speedup 1.0000x reference)
#include <cuda_runtime.h>
#include <cstdint>

// TSBRNN: B=8192 rows, T=4096, per-row 2-state swap recurrence.
// R9: register-direct dataflow. Each lane owns one row; per tile it reads its
// row's 256B directly with 16 LDG.128 (contiguous per lane -> sectors merge in
// MSHRs), double-buffered in registers. No smem input pipeline, no LDGSTS, no
// LDS except the 16KB broadcast aX table. Removes ~2/3 of per-tile LSU work.

namespace {
constexpr int T_LEN   = 4096;
constexpr int TT      = 64;              // timesteps per tile (256B per row)
constexpr int NT      = T_LEN / TT;      // 64 tiles
constexpr int THREADS = 64;              // 2 warps, 1 row per lane
constexpr int ROWS    = THREADS;         // 64 rows per CTA -> grid 128
constexpr int SMEM_BYTES = T_LEN * 4;    // aX table only (16KB)
}

__global__ void __launch_bounds__(THREADS, 1)
tsb_kernel(const float* __restrict__ x, const float* __restrict__ alpha_p,
           const float* __restrict__ beta_p, float* __restrict__ out) {
    extern __shared__ float aX[];        // alpha * x[0, t]

    const int tid = threadIdx.x;
    const float alpha  = __ldg(alpha_p);
    const float beta   = __ldg(beta_p);
    const float omb    = 1.0f - beta;
    const float nalpha = -alpha;

    // Stage the global level-driver sequence once per CTA (L2-hot)
#pragma no_unroll
    for (int i = tid; i < T_LEN / 4; i += THREADS) {
        float4 v = __ldg(reinterpret_cast<const float4*>(x) + i);
        v.x *= alpha; v.y *= alpha; v.z *= alpha; v.w *= alpha;
        reinterpret_cast<float4*>(aX)[i] = v;
    }
    __syncthreads();   // only barrier

    const int row = blockIdx.x * ROWS + tid;
    const float4* xr = reinterpret_cast<const float4*>(x + (size_t)row * T_LEN);
    float* og = out + (size_t)row * T_LEN;

    float4 b0[16], b1[16];
    // Prologue: tile 0 into b0
#pragma unroll
    for (int j = 0; j < 16; ++j) b0[j] = __ldg(xr + j);

    float A = 0.0f, Bs = 0.0f;

#define TSB_STEP(xval, aval, oval)                      \
    {                                                   \
        float nz  = fminf(fabsf(xval), 1.0f);           \
        float bnz = fminf(fabsf(xval), beta);           \
        float t1  = fmaf(nalpha, A, aval);              \
        float Bn  = fmaf(nz, t1, A);                    \
        float An  = fmaf(Bs, omb, bnz);                 \
        oval = An * Bn; A = An; Bs = Bn;                \
    }

#define TSB_TILE(BUF, t)                                                     \
    {                                                                        \
        const float* aXt = aX + (t) * TT;                                    \
        float* o = og + (size_t)(t) * TT;                                    \
        _Pragma("unroll")                                                    \
        for (int j2 = 0; j2 < 8; ++j2) {                                     \
            float4 xv0 = BUF[2 * j2];                                        \
            float4 xv1 = BUF[2 * j2 + 1];                                    \
            float4 av0 = *reinterpret_cast<const float4*>(aXt + j2 * 8);     \
            float4 av1 = *reinterpret_cast<const float4*>(aXt + j2 * 8 + 4); \
            float4 o0, o1;                                                   \
            TSB_STEP(xv0.x, av0.x, o0.x);                                    \
            TSB_STEP(xv0.y, av0.y, o0.y);                                    \
            TSB_STEP(xv0.z, av0.z, o0.z);                                    \
            TSB_STEP(xv0.w, av0.w, o0.w);                                    \
            TSB_STEP(xv1.x, av1.x, o1.x);                                    \
            TSB_STEP(xv1.y, av1.y, o1.y);                                    \
            TSB_STEP(xv1.z, av1.z, o1.z);                                    \
            TSB_STEP(xv1.w, av1.w, o1.w);                                    \
            *reinterpret_cast<float4*>(o + j2 * 8)     = o0;                 \
            *reinterpret_cast<float4*>(o + j2 * 8 + 4) = o1;                 \
        }                                                                    \
    }

    // Main loop, 2 tiles per iteration (register double buffer).
    // Load-ahead clamps to the last tile (harmless L2-hit re-read).
#pragma no_unroll
    for (int t = 0; t < NT; t += 2) {
        {   // load tile t+1 into b1, then compute tile t from b0
            int lt = (t + 1 < NT) ? (t + 1) : (NT - 1);
            const float4* src = xr + lt * (TT / 4);
#pragma unroll
            for (int j = 0; j < 16; ++j) b1[j] = __ldg(src + j);
        }
        TSB_TILE(b0, t);
        {   // load tile t+2 into b0, then compute tile t+1 from b1
            int lt = (t + 2 < NT) ? (t + 2) : (NT - 1);
            const float4* src = xr + lt * (TT / 4);
#pragma unroll
            for (int j = 0; j < 16; ++j) b0[j] = __ldg(src + j);
        }
        TSB_TILE(b1, t + 1);
    }
#undef TSB_TILE
#undef TSB_STEP
}

extern "C" void kernel_launch(void* const* d_in, const int* in_sizes, int n_in,
                              void* d_out, int out_size) {
    const float* x       = (const float*)d_in[0];   // (B, T, 1) float32
    const float* alpha_p = (const float*)d_in[1];   // (1, 1)
    const float* beta_p  = (const float*)d_in[2];   // (1, 1)
    float* out = (float*)d_out;

    int batch = in_sizes[0] / T_LEN;                // 8192
    int grid  = batch / ROWS;                       // 128 CTAs

    cudaFuncSetAttribute(tsb_kernel, cudaFuncAttributeMaxDynamicSharedMemorySize,
                         SMEM_BYTES);
    tsb_kernel<<<grid, THREADS, SMEM_BYTES>>>(x, alpha_p, beta_p, out);
}

// round 10
// speedup vs baseline: 1.8008x; 1.8008x over previous
#include <cuda_runtime.h>
#include <cstdint>

// TSBRNN: B=8192 rows, T=4096, per-row 2-state swap recurrence.
// R10 = R2 + COALESCED STORES. Diagnosis across R1-R9: the binder is L1tex
// wavefront throughput (~1/cyc/SM); R2's scattered STG.128 (32 lines/instr,
// 512 wf/tile) dominated. Outputs now stage through an 8KB/warp smem tile
// (conflict-free swizzle) and leave via 16 STG.128 of 2x256B contiguous
// (4 lines/instr) -> 4.5x fewer wavefronts; DRAM becomes the limit.

namespace {
constexpr int T_LEN   = 4096;
constexpr int TT      = 64;              // timesteps per tile
constexpr int NT      = T_LEN / TT;      // 64 tiles
constexpr int WROWS   = 32;              // rows per warp (1 row/lane)
constexpr int WARPS   = 2;
constexpr int THREADS = 32 * WARPS;      // 64
constexpr int ROWS    = WROWS * WARPS;   // 64 rows per CTA -> grid 128
constexpr int STAGES  = 8;
constexpr int TILE_F  = WROWS * TT;      // 2048 floats = 8KB per stage
constexpr int WIN_F   = STAGES * TILE_F; // 64KB input ring per warp
constexpr int SMEM_FLOATS = WARPS * WIN_F + WARPS * TILE_F + T_LEN;
constexpr int SMEM_BYTES  = SMEM_FLOATS * 4;  // 128KB + 16KB + 16KB = 160KB
}

__device__ __forceinline__ void cp_async16(uint32_t dst, const void* src) {
    asm volatile("cp.async.cg.shared.global [%0], [%1], 16;\n" :: "r"(dst), "l"(src));
}
__device__ __forceinline__ void cp_commit() {
    asm volatile("cp.async.commit_group;\n" ::: "memory");
}
template <int N>
__device__ __forceinline__ void cp_wait() {
    asm volatile("cp.async.wait_group %0;\n" :: "n"(N) : "memory");
}

__global__ void __launch_bounds__(THREADS, 1)
tsb_kernel(const float* __restrict__ x, const float* __restrict__ alpha_p,
           const float* __restrict__ beta_p, float* __restrict__ out) {
    extern __shared__ float smem[];
    float* obuf_all = smem + WARPS * WIN_F;           // 2 x 8KB output tiles
    float* aX       = obuf_all + WARPS * TILE_F;      // alpha * x[0, t]

    const int tid  = threadIdx.x;
    const int wid  = tid >> 5;
    const int lane = tid & 31;
    const float alpha  = __ldg(alpha_p);
    const float beta   = __ldg(beta_p);
    const float omb    = 1.0f - beta;
    const float nalpha = -alpha;

    // One-time staging of the global level-driver sequence
#pragma no_unroll
    for (int i = tid; i < T_LEN / 4; i += THREADS) {
        float4 v = __ldg(reinterpret_cast<const float4*>(x) + i);
        v.x *= alpha; v.y *= alpha; v.z *= alpha; v.w *= alpha;
        reinterpret_cast<float4*>(aX)[i] = v;
    }
    __syncthreads();   // ONLY CTA barrier

    const int row_base = blockIdx.x * ROWS + wid * WROWS;
    float* wbuf = smem + wid * WIN_F;
    float* obuf = obuf_all + wid * TILE_F;
    const uint32_t wbuf_sa = (uint32_t)__cvta_generic_to_shared(wbuf);
    const float* xbase = x + (size_t)row_base * T_LEN;
    float* obase = out + (size_t)row_base * T_LEN;

    // Per-warp tile load: 16 cp.async/lane-group, coalesced global (4 lines/instr),
    // XOR-swizzled smem destination (conflict-free for compute LDS.128).
    auto load_tile = [&](int tile, int slot) {
        uint32_t sbase = wbuf_sa + (uint32_t)(slot * TILE_F) * 4u;
#pragma unroll
        for (int i = 0; i < 16; ++i) {
            int idx = lane + 32 * i;       // 0..511 (32 rows x 16 float4)
            int row = idx >> 4;
            int j4  = idx & 15;
            int js  = j4 ^ (row & 7);
            const float* src = xbase + (size_t)row * T_LEN + tile * TT + j4 * 4;
            cp_async16(sbase + (uint32_t)(row * TT + js * 4) * 4u, src);
        }
    };

    // Prologue: fill the 8-deep ring
#pragma unroll
    for (int k = 0; k < STAGES; ++k) {
        load_tile(k, k);
        cp_commit();
    }

    float A = 0.0f, Bs = 0.0f;
    const int swz = lane & 7;

#define TSB_STEP(xval, aval, oval)                      \
    {                                                   \
        float nz  = fminf(fabsf(xval), 1.0f);           \
        float bnz = fminf(fabsf(xval), beta);           \
        float t1  = fmaf(nalpha, A, aval);              \
        float Bn  = fmaf(nz, t1, A);                    \
        float An  = fmaf(Bs, omb, bnz);                 \
        oval = An * Bn; A = An; Bs = Bn;                \
    }

    for (int tile = 0; tile < NT; ++tile) {
        cp_wait<STAGES - 1>();   // per-thread cp.async group state

        const float* xr  = wbuf + (tile & (STAGES - 1)) * TILE_F + lane * TT;
        float*       orw = obuf + lane * TT;
        const float* aXt = aX + tile * TT;

        // Compute 64 steps; outputs -> smem tile (same swizzle as input)
#pragma unroll
        for (int j8 = 0; j8 < TT / 8; ++j8) {
            int j4a = (2 * j8) ^ swz;
            int j4b = j4a ^ 1;
            float4 xv0 = *reinterpret_cast<const float4*>(xr + j4a * 4);
            float4 xv1 = *reinterpret_cast<const float4*>(xr + j4b * 4);
            float4 av0 = *reinterpret_cast<const float4*>(aXt + j8 * 8);
            float4 av1 = *reinterpret_cast<const float4*>(aXt + j8 * 8 + 4);
            float4 o0, o1;
            TSB_STEP(xv0.x, av0.x, o0.x);
            TSB_STEP(xv0.y, av0.y, o0.y);
            TSB_STEP(xv0.z, av0.z, o0.z);
            TSB_STEP(xv0.w, av0.w, o0.w);
            TSB_STEP(xv1.x, av1.x, o1.x);
            TSB_STEP(xv1.y, av1.y, o1.y);
            TSB_STEP(xv1.z, av1.z, o1.z);
            TSB_STEP(xv1.w, av1.w, o1.w);
            *reinterpret_cast<float4*>(orw + j4a * 4) = o0;
            *reinterpret_cast<float4*>(orw + j4b * 4) = o1;
        }

        __syncwarp();   // all lanes' STS visible before cross-lane readback

        // Coalesced store: mirror of load pattern, 2 rows x 256B per STG wave
        // (4 lines per STG.128 instead of 32).
#pragma unroll
        for (int i = 0; i < 16; ++i) {
            int idx = lane + 32 * i;
            int row = idx >> 4;
            int j4  = idx & 15;
            int js  = j4 ^ (row & 7);
            float4 v = *reinterpret_cast<const float4*>(obuf + row * TT + js * 4);
            *reinterpret_cast<float4*>(obase + (size_t)row * T_LEN + tile * TT + j4 * 4) = v;
        }

        __syncwarp();   // readback done before next tile overwrites obuf

        // Refill the input slot just consumed (8 tiles ahead)
        int nt = tile + STAGES;
        if (nt < NT)
            load_tile(nt, tile & (STAGES - 1));
        cp_commit();   // always commit: keeps wait_group accounting aligned
    }
#undef TSB_STEP
}

extern "C" void kernel_launch(void* const* d_in, const int* in_sizes, int n_in,
                              void* d_out, int out_size) {
    const float* x       = (const float*)d_in[0];   // (B, T, 1) float32
    const float* alpha_p = (const float*)d_in[1];   // (1, 1)
    const float* beta_p  = (const float*)d_in[2];   // (1, 1)
    float* out = (float*)d_out;

    int batch = in_sizes[0] / T_LEN;                // 8192
    int grid  = batch / ROWS;                       // 128 CTAs

    cudaFuncSetAttribute(tsb_kernel, cudaFuncAttributeMaxDynamicSharedMemorySize,
                         SMEM_BYTES);
    tsb_kernel<<<grid, THREADS, SMEM_BYTES>>>(x, alpha_p, beta_p, out);
}

// round 11
// speedup vs baseline: 2.0827x; 1.1565x over previous
#include <cuda_runtime.h>
#include <cstdint>

// TSBRNN: B=8192 rows, T=4096, per-row 2-state swap recurrence.
// R11 = R10 (coalesced loads AND stores) + 4 warps/CTA, one per SMSP:
// 2 rowgroups x 2 T-chunks, chunk 1 warms up 256 steps (contraction-safe,
// validated). Every warp exactly 34 tiles; grid 128 = one wave, 1 CTA/SM.
// R10 showed per-warp issue-bound (71% issue-active) with memory loafing
// (L2 24%, DRAM 46%) -> fill the two idle SMSPs, halve per-warp work.

namespace {
constexpr int T_LEN   = 4096;
constexpr int TT      = 64;               // timesteps per tile
constexpr int WROWS   = 32;               // rows per warp (1 row/lane)
constexpr int WARPS   = 4;                // 2 rowgroups x 2 T-chunks
constexpr int THREADS = 32 * WARPS;       // 128
constexpr int ROWS    = 64;               // rows per CTA -> grid 128 (one wave)
constexpr int STAGES  = 5;
constexpr int TILE_F  = WROWS * TT;       // 2048 floats = 8KB per stage
constexpr int WIN_F   = STAGES * TILE_F;  // 40KB input ring per warp
constexpr int SMEM_FLOATS = WARPS * WIN_F + WARPS * TILE_F + T_LEN;
constexpr int SMEM_BYTES  = SMEM_FLOATS * 4;   // 160KB + 32KB + 16KB = 208KB
constexpr int WARM       = 256;           // warmup steps for chunk 1 (4 tiles)
constexpr int E0         = 2176;          // chunk-0 emit length (34 tiles)
constexpr int N_TILES    = 34;            // uniform tiles per warp
constexpr int WARM_TILES = WARM / TT;     // 4
}

__device__ __forceinline__ void cp_async16(uint32_t dst, const void* src) {
    asm volatile("cp.async.cg.shared.global [%0], [%1], 16;\n" :: "r"(dst), "l"(src));
}
__device__ __forceinline__ void cp_commit() {
    asm volatile("cp.async.commit_group;\n" ::: "memory");
}
template <int N>
__device__ __forceinline__ void cp_wait() {
    asm volatile("cp.async.wait_group %0;\n" :: "n"(N) : "memory");
}

__global__ void __launch_bounds__(THREADS, 1)
tsb_kernel(const float* __restrict__ x, const float* __restrict__ alpha_p,
           const float* __restrict__ beta_p, float* __restrict__ out) {
    extern __shared__ float smem[];
    float* obuf_all = smem + WARPS * WIN_F;        // 4 x 8KB output tiles
    float* aX       = obuf_all + WARPS * TILE_F;   // alpha * x[0, t]

    const int tid  = threadIdx.x;
    const int wid  = tid >> 5;
    const int lane = tid & 31;
    const float alpha  = __ldg(alpha_p);
    const float beta   = __ldg(beta_p);
    const float omb    = 1.0f - beta;
    const float nalpha = -alpha;

    // One-time staging of the global level-driver sequence
#pragma no_unroll
    for (int i = tid; i < T_LEN / 4; i += THREADS) {
        float4 v = __ldg(reinterpret_cast<const float4*>(x) + i);
        v.x *= alpha; v.y *= alpha; v.z *= alpha; v.w *= alpha;
        reinterpret_cast<float4*>(aX)[i] = v;
    }
    __syncthreads();   // ONLY CTA barrier

    const int rowgrp = wid >> 1;           // 0..1
    const int chunk  = wid & 1;            // 0..1 T-chunk
    // Chunk 0: emits [0, 2176). Chunk 1: loads from 1920, warms 4 tiles,
    // emits [2176, 4096). Both run exactly 34 tiles.
    const int t_load0 = (chunk == 0) ? 0 : (E0 - WARM);   // 0 or 1920
    const int warm_tl = (chunk == 0) ? 0 : WARM_TILES;

    const int row_base = blockIdx.x * ROWS + rowgrp * WROWS;
    float* wbuf = smem + wid * WIN_F;
    float* obuf = obuf_all + wid * TILE_F;
    const uint32_t wbuf_sa = (uint32_t)__cvta_generic_to_shared(wbuf);
    const float* xbase = x + (size_t)row_base * T_LEN + t_load0;
    float* obase = out + (size_t)row_base * T_LEN + t_load0;

    // Per-warp tile load: coalesced global (2 rows x 256B per instr -> 4 lines),
    // XOR-swizzled smem destination (conflict-free for compute LDS.128).
    auto load_tile = [&](int tile, int slot) {
        uint32_t sbase = wbuf_sa + (uint32_t)(slot * TILE_F) * 4u;
#pragma unroll
        for (int i = 0; i < 16; ++i) {
            int idx = lane + 32 * i;       // 0..511 (32 rows x 16 float4)
            int row = idx >> 4;
            int j4  = idx & 15;
            int js  = j4 ^ (row & 7);
            const float* src = xbase + (size_t)row * T_LEN + tile * TT + j4 * 4;
            cp_async16(sbase + (uint32_t)(row * TT + js * 4) * 4u, src);
        }
    };

    // Prologue: fill the ring
#pragma unroll
    for (int k = 0; k < STAGES; ++k) {
        load_tile(k, k);
        cp_commit();
    }

    float A = 0.0f, Bs = 0.0f;
    const int swz = lane & 7;

#define TSB_STEP(xval, aval, oval)                      \
    {                                                   \
        float nz  = fminf(fabsf(xval), 1.0f);           \
        float bnz = fminf(fabsf(xval), beta);           \
        float t1  = fmaf(nalpha, A, aval);              \
        float Bn  = fmaf(nz, t1, A);                    \
        float An  = fmaf(Bs, omb, bnz);                 \
        oval = An * Bn; A = An; Bs = Bn;                \
    }

    for (int tile = 0; tile < N_TILES; ++tile) {
        cp_wait<STAGES - 1>();   // per-thread cp.async group state

        const float* xr  = wbuf + (tile % STAGES) * TILE_F + lane * TT;
        float*       orw = obuf + lane * TT;
        const float* aXt = aX + t_load0 + tile * TT;
        const bool emit  = (tile >= warm_tl);

        // Compute 64 steps; outputs -> smem tile (same swizzle as input)
#pragma unroll
        for (int j8 = 0; j8 < TT / 8; ++j8) {
            int j4a = (2 * j8) ^ swz;
            int j4b = j4a ^ 1;
            float4 xv0 = *reinterpret_cast<const float4*>(xr + j4a * 4);
            float4 xv1 = *reinterpret_cast<const float4*>(xr + j4b * 4);
            float4 av0 = *reinterpret_cast<const float4*>(aXt + j8 * 8);
            float4 av1 = *reinterpret_cast<const float4*>(aXt + j8 * 8 + 4);
            float4 o0, o1;
            TSB_STEP(xv0.x, av0.x, o0.x);
            TSB_STEP(xv0.y, av0.y, o0.y);
            TSB_STEP(xv0.z, av0.z, o0.z);
            TSB_STEP(xv0.w, av0.w, o0.w);
            TSB_STEP(xv1.x, av1.x, o1.x);
            TSB_STEP(xv1.y, av1.y, o1.y);
            TSB_STEP(xv1.z, av1.z, o1.z);
            TSB_STEP(xv1.w, av1.w, o1.w);
            *reinterpret_cast<float4*>(orw + j4a * 4) = o0;
            *reinterpret_cast<float4*>(orw + j4b * 4) = o1;
        }

        __syncwarp();   // all lanes' STS visible before cross-lane readback

        if (emit) {
            // Coalesced store: mirror of load pattern (4 lines per STG.128)
#pragma unroll
            for (int i = 0; i < 16; ++i) {
                int idx = lane + 32 * i;
                int row = idx >> 4;
                int j4  = idx & 15;
                int js  = j4 ^ (row & 7);
                float4 v = *reinterpret_cast<const float4*>(obuf + row * TT + js * 4);
                *reinterpret_cast<float4*>(
                    obase + (size_t)row * T_LEN + tile * TT + j4 * 4) = v;
            }
        }

        __syncwarp();   // readback done before next tile overwrites obuf

        // Refill the slot just consumed
        int nt = tile + STAGES;
        if (nt < N_TILES)
            load_tile(nt, nt % STAGES);
        cp_commit();   // always commit: keeps wait_group accounting aligned
    }
#undef TSB_STEP
}

extern "C" void kernel_launch(void* const* d_in, const int* in_sizes, int n_in,
                              void* d_out, int out_size) {
    const float* x       = (const float*)d_in[0];   // (B, T, 1) float32
    const float* alpha_p = (const float*)d_in[1];   // (1, 1)
    const float* beta_p  = (const float*)d_in[2];   // (1, 1)
    float* out = (float*)d_out;

    int batch = in_sizes[0] / T_LEN;                // 8192
    int grid  = batch / ROWS;                       // 128 CTAs -> one wave

    cudaFuncSetAttribute(tsb_kernel, cudaFuncAttributeMaxDynamicSharedMemorySize,
                         SMEM_BYTES);
    tsb_kernel<<<grid, THREADS, SMEM_BYTES>>>(x, alpha_p, beta_p, out);
}